// round 3
// baseline (speedup 1.0000x reference)
#include <cuda_runtime.h>
#include <cuda_bf16.h>
#include <cstdint>

typedef unsigned long long u64;

// ---------------------------------------------------------------------------
// Packed fp32x2 helpers (sm_100+ PTX; ptxas never emits FFMA2 from C++)
// ---------------------------------------------------------------------------
__device__ __forceinline__ u64 pack2(float lo, float hi) {
    u64 r; asm("mov.b64 %0, {%1, %2};" : "=l"(r) : "f"(lo), "f"(hi)); return r;
}
__device__ __forceinline__ void unpack2(u64 v, float& lo, float& hi) {
    asm("mov.b64 {%0, %1}, %2;" : "=f"(lo), "=f"(hi) : "l"(v));
}
__device__ __forceinline__ void ffma2(u64& d, u64 a, u64 b) {
    asm("fma.rn.f32x2 %0, %1, %2, %0;" : "+l"(d) : "l"(a), "l"(b));
}

// ---------------------------------------------------------------------------
// Scratch (device globals -- no runtime allocation allowed)
// ---------------------------------------------------------------------------
__device__ float g_conv1[64 * 64 * 56 * 56];   // conv1 output (relu'd)  ~51.4MB
__device__ float g_part[4 * 64 * 256];         // conv2 partial pooled sums [rt][n][oc]
__device__ float g_mu[64 * 32];
__device__ float g_kappa[64];
__device__ float g_z[64 * 32];

// ---------------------------------------------------------------------------
// Kernel 1: conv1 7x7 stride4 pad3, 6->64 ch, + bias + relu  (f32x2 FMA)
// tile: 64 oc x 56 cols x 4 rows per block. thread: 8 oc x 8 cols.
// ---------------------------------------------------------------------------
#define XR1 233   // padded smem row stride (4*233 % 32 = 4 -> conflict-free rows)

__global__ __launch_bounds__(224, 2)
void conv1_kernel(const float* __restrict__ x, const float* __restrict__ W1,
                  const float* __restrict__ b1) {
    __shared__ float ws[49 * 64];       // [q][oc]
    __shared__ float xs[19 * XR1];      // one ci, 19 input rows x 227 cols (padded)

    const int rt  = blockIdx.x;         // 0..13 (4 output rows each)
    const int n   = blockIdx.y;         // batch
    const int tid = threadIdx.x;        // 224 threads
    const int og  = tid & 7;            // oc group (8 oc each)
    const int row = (tid >> 3) & 3;     // output row within tile
    const int cg  = tid >> 5;           // col group (8 cols each), 0..6

    u64 acc[8][4];                      // [oc][col-pair] packed fp32x2
#pragma unroll
    for (int o = 0; o < 8; o++)
#pragma unroll
        for (int p = 0; p < 4; p++) acc[o][p] = 0ull;

    for (int ci = 0; ci < 6; ci++) {
        __syncthreads();
        for (int i = tid; i < 3136; i += 224) {
            int oc = i / 49, q = i - oc * 49;
            ws[q * 64 + oc] = W1[oc * 294 + ci * 49 + q];
        }
        const float* xb = x + ((size_t)(n * 6 + ci)) * 224 * 224;
        for (int i = tid; i < 19 * 227; i += 224) {
            int r = i / 227, c = i - r * 227;
            int ih = rt * 16 - 3 + r;
            int iw = c - 3;
            float v = 0.f;
            if (ih >= 0 && ih < 224 && iw >= 0) v = xb[ih * 224 + iw];
            xs[r * XR1 + c] = v;
        }
        __syncthreads();

        for (int kh = 0; kh < 7; kh++) {
            const float* xrow = &xs[(row * 4 + kh) * XR1 + cg * 32];
#pragma unroll
            for (int kw = 0; kw < 7; kw++) {
                const int q = kh * 7 + kw;
                const float4 wa = *(const float4*)&ws[q * 64 + og * 8];
                const float4 wb = *(const float4*)&ws[q * 64 + og * 8 + 4];
                u64 w2[8];
                w2[0] = pack2(wa.x, wa.x); w2[1] = pack2(wa.y, wa.y);
                w2[2] = pack2(wa.z, wa.z); w2[3] = pack2(wa.w, wa.w);
                w2[4] = pack2(wb.x, wb.x); w2[5] = pack2(wb.y, wb.y);
                w2[6] = pack2(wb.z, wb.z); w2[7] = pack2(wb.w, wb.w);
                u64 xp[4];
#pragma unroll
                for (int pp = 0; pp < 4; pp++)
                    xp[pp] = pack2(xrow[(2 * pp) * 4 + kw], xrow[(2 * pp + 1) * 4 + kw]);
#pragma unroll
                for (int o = 0; o < 8; o++)
#pragma unroll
                    for (int pp = 0; pp < 4; pp++)
                        ffma2(acc[o][pp], xp[pp], w2[o]);
            }
        }
    }

    const int oh = rt * 4 + row;
#pragma unroll
    for (int o = 0; o < 8; o++) {
        const int oc = og * 8 + o;
        const float bv = b1[oc];
        float* outp = &g_conv1[(((size_t)n * 64 + oc) * 56 + oh) * 56 + cg * 8];
        float t[8];
#pragma unroll
        for (int pp = 0; pp < 4; pp++) unpack2(acc[o][pp], t[2 * pp], t[2 * pp + 1]);
#pragma unroll
        for (int p = 0; p < 8; p += 4) {
            float4 v;
            v.x = fmaxf(t[p + 0] + bv, 0.f);
            v.y = fmaxf(t[p + 1] + bv, 0.f);
            v.z = fmaxf(t[p + 2] + bv, 0.f);
            v.w = fmaxf(t[p + 3] + bv, 0.f);
            *(float4*)&outp[p] = v;
        }
    }
}

// ---------------------------------------------------------------------------
// Kernel 2: conv2 3x3 stride2 pad1, 64->256 ch, + bias + relu + pooled sums
// (f32x2 FMA; conv2 activations never hit HBM)
// tile: 64 oc x 28 cols x 8 rows. thread: 8 oc x 4 cols x 2 rows.
// ---------------------------------------------------------------------------
#define XR2 59
#define CK  4

__global__ __launch_bounds__(224, 2)
void conv2_kernel(const float* __restrict__ W2, const float* __restrict__ b2) {
    __shared__ float ws[CK * 9 * 64];
    __shared__ float xs[CK * 17 * XR2];
    __shared__ float red[224 * 8];

    const int rt  = blockIdx.x;
    const int ot  = blockIdx.y;
    const int n   = blockIdx.z;
    const int tid = threadIdx.x;
    const int og   = tid & 7;
    const int rowg = (tid >> 3) & 3;
    const int colg = tid >> 5;

    u64 acc[8][4];   // [oc][rr*2 + col-pair] packed fp32x2
#pragma unroll
    for (int o = 0; o < 8; o++)
#pragma unroll
        for (int p = 0; p < 4; p++) acc[o][p] = 0ull;

    for (int cc = 0; cc < 64 / CK; cc++) {
        __syncthreads();
        for (int i = tid; i < CK * 9 * 64; i += 224) {
            int oc = i / (CK * 9), rsd = i - oc * (CK * 9);
            int cil = rsd / 9, q = rsd - cil * 9;
            ws[(cil * 9 + q) * 64 + oc] =
                W2[(((size_t)(ot * 64 + oc)) * 64 + (cc * CK + cil)) * 9 + q];
        }
        for (int i = tid; i < CK * 17 * 57; i += 224) {
            int cil = i / (17 * 57);
            int rsd = i - cil * (17 * 57);
            int r = rsd / 57, c = rsd - r * 57;
            int ih = rt * 16 - 1 + r;
            int iw = c - 1;
            float v = 0.f;
            if (ih >= 0 && ih < 56 && iw >= 0 && iw < 56)
                v = g_conv1[(((size_t)n * 64 + (cc * CK + cil)) * 56 + ih) * 56 + iw];
            xs[(cil * 17 + r) * XR2 + c] = v;
        }
        __syncthreads();

#pragma unroll
        for (int cil = 0; cil < CK; cil++) {
#pragma unroll
            for (int kh = 0; kh < 3; kh++) {
#pragma unroll
                for (int kw = 0; kw < 3; kw++) {
                    const int q = kh * 3 + kw;
                    const float4 wa = *(const float4*)&ws[(cil * 9 + q) * 64 + og * 8];
                    const float4 wb = *(const float4*)&ws[(cil * 9 + q) * 64 + og * 8 + 4];
                    u64 w2[8];
                    w2[0] = pack2(wa.x, wa.x); w2[1] = pack2(wa.y, wa.y);
                    w2[2] = pack2(wa.z, wa.z); w2[3] = pack2(wa.w, wa.w);
                    w2[4] = pack2(wb.x, wb.x); w2[5] = pack2(wb.y, wb.y);
                    w2[6] = pack2(wb.z, wb.z); w2[7] = pack2(wb.w, wb.w);
                    u64 xp[4];
#pragma unroll
                    for (int rr = 0; rr < 2; rr++) {
                        const float* xr = &xs[(cil * 17 + (rowg * 2 + rr) * 2 + kh) * XR2];
#pragma unroll
                        for (int pp = 0; pp < 2; pp++)
                            xp[rr * 2 + pp] =
                                pack2(xr[(colg * 4 + 2 * pp) * 2 + kw],
                                      xr[(colg * 4 + 2 * pp + 1) * 2 + kw]);
                    }
#pragma unroll
                    for (int o = 0; o < 8; o++)
#pragma unroll
                        for (int pp = 0; pp < 4; pp++)
                            ffma2(acc[o][pp], xp[pp], w2[o]);
                }
            }
        }
    }

    const int oh0 = rt * 8 + rowg * 2;
    float s[8];
#pragma unroll
    for (int o = 0; o < 8; o++) {
        const float bv = b2[ot * 64 + og * 8 + o];
        float t[8];
#pragma unroll
        for (int pp = 0; pp < 4; pp++) unpack2(acc[o][pp], t[2 * pp], t[2 * pp + 1]);
        float acc_s = 0.f;
#pragma unroll
        for (int rr = 0; rr < 2; rr++) {
            if (oh0 + rr < 28) {
#pragma unroll
                for (int pc = 0; pc < 4; pc++)
                    acc_s += fmaxf(t[rr * 4 + pc] + bv, 0.f);
            }
        }
        s[o] = acc_s;
    }
#pragma unroll
    for (int o = 0; o < 8; o++) red[tid * 8 + o] = s[o];
    __syncthreads();
    if (tid < 64) {
        const int o = tid & 7, ogr = tid >> 3;
        float t = 0.f;
        for (int k = 0; k < 28; k++) t += red[(ogr + 8 * k) * 8 + o];
        g_part[((size_t)rt * 64 + n) * 256 + ot * 64 + tid] = t;
    }
}

// ---------------------------------------------------------------------------
// Kernel 3: mean-pool finish + fc(256->512) + mu head + kappa head
// ---------------------------------------------------------------------------
__global__ void head_kernel(const float* __restrict__ Wh, const float* __restrict__ bh,
                            const float* __restrict__ Wmu, const float* __restrict__ bmu,
                            const float* __restrict__ Wk, const float* __restrict__ bk,
                            float* __restrict__ d_out, int out_size) {
    __shared__ float p[256];
    __shared__ float hs[512];
    __shared__ float ms[32];
    __shared__ float kap;

    const int b = blockIdx.x, t = threadIdx.x;

    if (t < 256) {
        float s = 0.f;
        for (int rt = 0; rt < 4; rt++) s += g_part[((size_t)rt * 64 + b) * 256 + t];
        p[t] = s / 784.0f;
    }
    __syncthreads();

    float hv = bh[t];
    for (int k = 0; k < 256; k++) hv += p[k] * Wh[k * 512 + t];
    hs[t] = hv;
    __syncthreads();

    if (t < 32) {
        float m = bmu[t];
        for (int k = 0; k < 512; k++) m += hs[k] * Wmu[k * 32 + t];
        ms[t] = m;
    }
    if (t >= 32 && t < 64) {
        float s2 = 0.f;
        for (int k = t - 32; k < 512; k += 32) s2 += hs[k] * Wk[k];
        for (int off = 16; off; off >>= 1) s2 += __shfl_down_sync(0xffffffffu, s2, off);
        if (t == 32) {
            float xk = s2 + bk[0];
            float sp = fmaxf(xk, 0.f) + log1pf(expf(-fabsf(xk)));
            kap = sp + 1.0f;
        }
    }
    __syncthreads();

    if (t < 32) {
        float m = ms[t];
        float ss = m * m;
        for (int off = 16; off; off >>= 1) ss += __shfl_xor_sync(0xffffffffu, ss, off);
        float nrm = sqrtf(fmaxf(ss, 1e-24f));
        float muv = m / nrm;
        g_mu[b * 32 + t] = muv;
        if (out_size >= 2560) d_out[448 + b * 32 + t] = muv;
    }
    if (t == 0) {
        g_kappa[b] = kap;
        if (out_size >= 2560) d_out[448 + 2048 + b] = kap;
    }
}

// ---------------------------------------------------------------------------
// Threefry-2x32 (JAX/XLA exact), partitionable semantics
// ---------------------------------------------------------------------------
__device__ __forceinline__ uint32_t rotl32(uint32_t x, int d) {
    return (x << d) | (x >> (32 - d));
}

__device__ void threefry2x32(uint32_t k0, uint32_t k1, uint32_t c0, uint32_t c1,
                             uint32_t& o0, uint32_t& o1) {
    uint32_t ks2 = k0 ^ k1 ^ 0x1BD11BDAu;
    uint32_t x0 = c0 + k0, x1 = c1 + k1;
#define TF_RND(R) { x0 += x1; x1 = rotl32(x1, R); x1 ^= x0; }
    TF_RND(13) TF_RND(15) TF_RND(26) TF_RND(6)
    x0 += k1;  x1 += ks2 + 1u;
    TF_RND(17) TF_RND(29) TF_RND(16) TF_RND(24)
    x0 += ks2; x1 += k0 + 2u;
    TF_RND(13) TF_RND(15) TF_RND(26) TF_RND(6)
    x0 += k0;  x1 += k1 + 3u;
    TF_RND(17) TF_RND(29) TF_RND(16) TF_RND(24)
    x0 += k1;  x1 += ks2 + 4u;
    TF_RND(13) TF_RND(15) TF_RND(26) TF_RND(6)
    x0 += ks2; x1 += k0 + 5u;
#undef TF_RND
    o0 = x0; o1 = x1;
}

__device__ __forceinline__ uint32_t tf_bits32(uint32_t k0, uint32_t k1, uint32_t idx) {
    uint32_t a, b;
    threefry2x32(k0, k1, 0u, idx, a, b);
    return a ^ b;
}

__device__ __forceinline__ float bits_to_unit(uint32_t bits) {
    return __uint_as_float((bits >> 9) | 0x3f800000u) - 1.0f;
}

__device__ float erfinv_xla(float x) {
    float w = -log1pf(-x * x);
    float p;
    if (w < 5.0f) {
        w = w - 2.5f;
        p = 2.81022636e-08f;
        p = 3.43273939e-07f + p * w;
        p = -3.5233877e-06f + p * w;
        p = -4.39150654e-06f + p * w;
        p = 0.00021858087f + p * w;
        p = -0.00125372503f + p * w;
        p = -0.00417768164f + p * w;
        p = 0.246640727f + p * w;
        p = 1.50140941f + p * w;
    } else {
        w = sqrtf(w) - 3.0f;
        p = -0.000200214257f;
        p = 0.000100950558f + p * w;
        p = 0.00134934322f + p * w;
        p = -0.00367342844f + p * w;
        p = 0.00573950773f + p * w;
        p = -0.0076224613f + p * w;
        p = 0.00943887047f + p * w;
        p = 1.00167406f + p * w;
        p = 2.83297682f + p * w;
    }
    return p * x;
}

// ---------------------------------------------------------------------------
// Kernel 4: vMF Wood sampling, 64 blocks x 32 threads (block = batch element)
// ---------------------------------------------------------------------------
__global__ void sample_kernel() {
    const int b = blockIdx.x;     // batch element
    const int t = threadIdx.x;    // lane 0..31

    uint32_t kw0, kw1, kv0, kv1;
    threefry2x32(0u, 42u, 0u, 0u, kw0, kw1);
    threefry2x32(0u, 42u, 0u, 1u, kv0, kv1);

    const float kappa = g_kappa[b];

    // rejection loop: all lanes compute redundantly (identical result, no divergence)
    float w = 0.f;
    bool accd = false;
    for (int i = 0; i < 10; i++) {
        uint32_t f0, f1;
        threefry2x32(kw0, kw1, 0u, (uint32_t)(2 * i), f0, f1);
        float u1 = bits_to_unit(tf_bits32(f0, f1, (uint32_t)b));
        float wc = 2.0f * u1 - 1.0f;
        threefry2x32(kw0, kw1, 0u, (uint32_t)(2 * i + 1), f0, f1);
        float u2 = bits_to_unit(tf_bits32(f0, f1, (uint32_t)b));

        float one_m = fmaxf(1.0f - wc * wc, 1e-40f);
        float log_p = kappa * wc + 14.5f * logf(one_m);
        float log_r = logf(u2 + 1e-40f);
        bool newly = (log_r + kappa <= log_p) && !accd;
        if (newly) { w = wc; accd = true; }
    }
    w = fminf(fmaxf(w, -1.0f), 1.0f);

    // tangent direction: one dim per lane (lane 31 inactive for v)
    const float LOv = -0.99999994f;
    float nv = 0.f;
    if (t < 31) {
        uint32_t idx = (uint32_t)(b * 31 + t);
        float f = bits_to_unit(tf_bits32(kv0, kv1, idx));
        float u = fmaxf(LOv, f * 2.0f + LOv);
        nv = 1.41421354f * erfinv_xla(u);
    }
    float ss = nv * nv;
    for (int off = 16; off; off >>= 1) ss += __shfl_xor_sync(0xffffffffu, ss, off);
    float rn = sqrtf(fmaxf(ss, 1e-24f));

    float sq = sqrtf(fmaxf(1.0f - w * w, 1e-40f));
    float zt = (t < 31) ? sq * (nv / rn) : w;

    // Householder: u = normalize(e_d - mu); z = zt - 2 (zt.u) u
    float e = ((t == 31) ? 1.0f : 0.0f) - g_mu[b * 32 + t];
    float ss2 = e * e;
    for (int off = 16; off; off >>= 1) ss2 += __shfl_xor_sync(0xffffffffu, ss2, off);
    float nn = sqrtf(fmaxf(ss2, 1e-24f));
    float uh = e / nn;
    float dp = zt * uh;
    for (int off = 16; off; off >>= 1) dp += __shfl_xor_sync(0xffffffffu, dp, off);
    g_z[b * 32 + t] = zt - 2.0f * dp * uh;
}

// ---------------------------------------------------------------------------
// Kernel 5: ResNetMLP head 32->512->512->32->7
// ---------------------------------------------------------------------------
__global__ void mlp_kernel(const float* __restrict__ M1, const float* __restrict__ bM1,
                           const float* __restrict__ M2, const float* __restrict__ bM2,
                           const float* __restrict__ M3, const float* __restrict__ bM3,
                           const float* __restrict__ M4, const float* __restrict__ bM4,
                           float* __restrict__ d_out) {
    __shared__ float zs[32];
    __shared__ float a1[512];
    __shared__ float a2[512];
    __shared__ float a3[32];
    const int b = blockIdx.x, t = threadIdx.x;

    if (t < 32) zs[t] = g_z[b * 32 + t];
    __syncthreads();

    float y = bM1[t];
    for (int k = 0; k < 32; k++) y += zs[k] * M1[k * 512 + t];
    a1[t] = fmaxf(y, 0.f);
    __syncthreads();

    y = bM2[t];
    for (int k = 0; k < 512; k++) y += a1[k] * M2[k * 512 + t];
    a2[t] = fmaxf(y, 0.f);
    __syncthreads();

    if (t < 32) {
        y = bM3[t];
        for (int k = 0; k < 512; k++) y += a2[k] * M3[k * 32 + t];
        a3[t] = fmaxf(y, 0.f);
    }
    __syncthreads();

    if (t < 7) {
        y = bM4[t];
        for (int k = 0; k < 32; k++) y += a3[k] * M4[k * 7 + t];
        d_out[b * 7 + t] = y;
    }
}

// ---------------------------------------------------------------------------
// Launch
// ---------------------------------------------------------------------------
extern "C" void kernel_launch(void* const* d_in, const int* in_sizes, int n_in,
                              void* d_out, int out_size) {
    const float* x   = (const float*)d_in[0];
    const float* W1  = (const float*)d_in[1];
    const float* b1  = (const float*)d_in[2];
    const float* W2  = (const float*)d_in[3];
    const float* b2  = (const float*)d_in[4];
    const float* Wh  = (const float*)d_in[5];
    const float* bh  = (const float*)d_in[6];
    const float* Wmu = (const float*)d_in[7];
    const float* bmu = (const float*)d_in[8];
    const float* Wk  = (const float*)d_in[9];
    const float* bk  = (const float*)d_in[10];
    const float* M1  = (const float*)d_in[11];
    const float* bM1 = (const float*)d_in[12];
    const float* M2  = (const float*)d_in[13];
    const float* bM2 = (const float*)d_in[14];
    const float* M3  = (const float*)d_in[15];
    const float* bM3 = (const float*)d_in[16];
    const float* M4  = (const float*)d_in[17];
    const float* bM4 = (const float*)d_in[18];
    float* out = (float*)d_out;

    conv1_kernel<<<dim3(14, 64), 224>>>(x, W1, b1);
    conv2_kernel<<<dim3(4, 4, 64), 224>>>(W2, b2);
    head_kernel<<<64, 512>>>(Wh, bh, Wmu, bmu, Wk, bk, out, out_size);
    sample_kernel<<<64, 32>>>();
    mlp_kernel<<<64, 512>>>(M1, bM1, M2, bM2, M3, bM3, M4, bM4, out);
}